// round 12
// baseline (speedup 1.0000x reference)
#include <cuda_runtime.h>
#include <cstdint>
#include <mma.h>
#include <math.h>

using namespace nvcuda;

#define NN 100000
#define MP 100096          // padded to 782*128
#define NE 400000
#define NG 4096
#define DD 128
#define HH 256
#define NL 20
#define G_EPS 1e-7f
#define BN_EPS 1e-5f

#define W1_ELEMS (NL*DD*HH)     // 655360
#define W2_ELEMS (NL*HH*HH)     // 1310720
#define W3_ELEMS (NL*HH*DD)     // 655360
#define W_TOTAL  (W1_ELEMS + W2_ELEMS + W3_ELEMS)

// ---------------- scratch (device globals; no allocations) ----------------
__device__ float g_h [MP*DD];
__device__ float g_h2[MP*DD];
__device__ float g_hh[MP*DD];
__device__ float g_a1[MP*HH];
__device__ float g_a2[MP*HH];
__device__ float g_Wh[W_TOTAL];
__device__ float g_Wl[W_TOTAL];
__device__ double g_sum[HH];
__device__ double g_sumsq[HH];
__device__ float g_mu[HH];
__device__ float g_rstd[HH];
__device__ int   g_deg[NN];
__device__ int   g_off[NN+1];
__device__ int   g_cursor[NN];
__device__ int   g_eid[NE];
__device__ int   g_partial[256];
__device__ float g_pool[NG];
__device__ int   g_cnt[NG];

#define SCAN_CHUNK 512
#define SCAN_NB ((NN + SCAN_CHUNK - 1) / SCAN_CHUNK)   // 196

// ---------------- small utility kernels ----------------
__global__ void k_init() {
    int i = blockIdx.x * blockDim.x + threadIdx.x;
    if (i < NN) { g_deg[i] = 0; g_cursor[i] = 0; }
    if (i < NG) { g_pool[i] = 0.f; g_cnt[i] = 0; }
    if (i < HH) { g_sum[i] = 0.0; g_sumsq[i] = 0.0; }
}

// ---------------- weight pre-split (hi/lo tf32 decomposition) --------------
__global__ void k_split(const float* __restrict__ w, float* __restrict__ wh,
                        float* __restrict__ wl, int n) {
    int i = blockIdx.x * blockDim.x + threadIdx.x;
    if (i < n) {
        float v = w[i];
        float hi = wmma::__float_to_tf32(v);
        wh[i] = hi;
        wl[i] = wmma::__float_to_tf32(v - hi);
    }
}

// ---------------- CSR build ----------------
__global__ void k_count_deg(const int* __restrict__ dst) {
    int e = blockIdx.x * blockDim.x + threadIdx.x;
    if (e < NE) atomicAdd(&g_deg[dst[e]], 1);
}
__global__ void k_scanA() {
    __shared__ int sm[SCAN_CHUNK];
    int tid = threadIdx.x;
    int gi = blockIdx.x * SCAN_CHUNK + tid;
    sm[tid] = (gi < NN) ? g_deg[gi] : 0;
    __syncthreads();
    for (int s = SCAN_CHUNK / 2; s > 0; s >>= 1) {
        if (tid < s) sm[tid] += sm[tid + s];
        __syncthreads();
    }
    if (tid == 0) g_partial[blockIdx.x] = sm[0];
}
__global__ void k_scanB() {
    __shared__ int sp[256];
    int tid = threadIdx.x;
    if (tid < SCAN_NB) sp[tid] = g_partial[tid];
    __syncthreads();
    if (tid == 0) {
        int run = 0;
        for (int i = 0; i < SCAN_NB; i++) { int v = sp[i]; sp[i] = run; run += v; }
        g_off[NN] = run;
    }
    __syncthreads();
    if (tid < SCAN_NB) g_partial[tid] = sp[tid];
}
__global__ void k_scanC() {
    __shared__ int sm[SCAN_CHUNK];
    int tid = threadIdx.x;
    int gi = blockIdx.x * SCAN_CHUNK + tid;
    int v = (gi < NN) ? g_deg[gi] : 0;
    sm[tid] = v;
    __syncthreads();
    for (int o = 1; o < SCAN_CHUNK; o <<= 1) {
        int t = (tid >= o) ? sm[tid - o] : 0;
        __syncthreads();
        sm[tid] += t;
        __syncthreads();
    }
    if (gi < NN) g_off[gi] = sm[tid] - v + g_partial[blockIdx.x];
}
__global__ void k_fill(const int* __restrict__ dst) {
    int e = blockIdx.x * blockDim.x + threadIdx.x;
    if (e < NE) {
        int d = dst[e];
        int p = atomicAdd(&g_cursor[d], 1);
        g_eid[g_off[d] + p] = e;
    }
}

// ---------------- atom encoder ----------------
__global__ void k_atom(const int* __restrict__ x, const float* __restrict__ emb,
                       float* __restrict__ h) {
    int n = blockIdx.x;
    int d = threadIdx.x;
    float s = 0.f;
    #pragma unroll
    for (int i = 0; i < 9; i++) {
        int id = x[n * 9 + i];
        s += emb[((size_t)i * 119 + id) * DD + d];
    }
    h[(size_t)n * DD + d] = s;
}

// ---------------- message + scatter softmax (online, staged metadata) -------
__global__ void k_msg(const float* __restrict__ h, const int* __restrict__ src,
                      const int* __restrict__ ea, const float* __restrict__ bond,
                      const float* __restrict__ tptr, float* __restrict__ hh) {
    __shared__ int ssrc[128];
    __shared__ int spack[128];
    int n = blockIdx.x;
    int d = threadIdx.x;
    float tv = __ldg(tptr);
    int beg = g_off[n], end = g_off[n + 1];
    float mrun = -3.4e38f;
    float dsum = 0.f, nsum = 0.f;
    for (int base = beg; base < end; base += 128) {
        int j = base + d;
        if (j < end) {
            int e = g_eid[j];
            ssrc[d]  = src[e];
            spack[d] = ea[e * 3 + 0] | (ea[e * 3 + 1] << 8) | (ea[e * 3 + 2] << 16);
        }
        __syncthreads();
        int cnt = min(end - base, 128);
        for (int jj = 0; jj < cnt; jj++) {
            int s = ssrc[jj];
            int pk = spack[jj];
            int a0 = pk & 255, a1 = (pk >> 8) & 255, a2 = pk >> 16;
            float m = __ldg(&h[(size_t)s * DD + d])
                    + __ldg(&bond[(size_t)a0 * DD + d])
                    + __ldg(&bond[(size_t)(6 + a1) * DD + d])
                    + __ldg(&bond[(size_t)(12 + a2) * DD + d]);
            m = fmaxf(m, 0.f) + G_EPS;
            float sc = m * tv;
            if (sc > mrun) {
                float corr = __expf(mrun - sc);   // first edge: exp(-big)=0
                dsum *= corr; nsum *= corr; mrun = sc;
            }
            float ex = __expf(sc - mrun);
            dsum += ex;
            nsum += m * ex;
        }
        __syncthreads();
    }
    float mo = (end > beg) ? (nsum / fmaxf(dsum, G_EPS)) : 0.f;
    hh[(size_t)n * DD + d] = h[(size_t)n * DD + d] + mo;
}

// ---------------- cp.async helpers ----------------
__device__ __forceinline__ void cp_async16(void* smem, const void* gmem) {
    unsigned int s = (unsigned int)__cvta_generic_to_shared(smem);
    asm volatile("cp.async.ca.shared.global [%0], [%1], 16;\n" :: "r"(s), "l"(gmem));
}
__device__ __forceinline__ void cp_commit() {
    asm volatile("cp.async.commit_group;\n");
}
template <int N>
__device__ __forceinline__ void cp_wait() {
    asm volatile("cp.async.wait_group %0;\n" :: "n"(N));
}

// ------------- 3xTF32 WMMA GEMM, cp.async 2-stage, pre-split weights --------
// C = A[M,K]@(Bh+Bl)[K,Nc] (+resid).  A split in-register; B pre-split.
// M multiple of 128 (padded), K multiple of 32, Nc multiple of 128.
#define GBK 32
#define LDA 36            // 32 + 4 pad
#define LDB 132           // 128 + 4 pad
#define SMEM_GEMM ((2*128*LDA + 4*GBK*LDB) * 4)   // 104448 bytes

__global__ __launch_bounds__(256) void k_gemm_tf32x3(
    const float* __restrict__ A,
    const float* __restrict__ Bh, const float* __restrict__ Bl,
    const float* __restrict__ resid, float* __restrict__ C,
    int K, int Nc)
{
    extern __shared__ float dsm[];
    float (*As)[128][LDA]  = (float(*)[128][LDA])dsm;
    float (*Bhs)[GBK][LDB] = (float(*)[GBK][LDB])(dsm + 2 * 128 * LDA);
    float (*Bls)[GBK][LDB] = (float(*)[GBK][LDB])(dsm + 2 * 128 * LDA + 2 * GBK * LDB);

    int tid = threadIdx.x;
    int wid = tid >> 5;
    int wm = wid & 3;        // warp row 0..3  -> 32 rows each
    int wn = wid >> 2;       // warp col 0..1  -> 64 cols each
    int row0 = blockIdx.x * 128;
    int col0 = blockIdx.y * 128;

    wmma::fragment<wmma::accumulator, 16, 16, 8, float> cf[2][4];
    if (resid) {
        #pragma unroll
        for (int i = 0; i < 2; i++)
            #pragma unroll
            for (int j = 0; j < 4; j++)
                wmma::load_matrix_sync(cf[i][j],
                    resid + (size_t)(row0 + wm * 32 + i * 16) * Nc + col0 + wn * 64 + j * 16,
                    Nc, wmma::mem_row_major);
    } else {
        #pragma unroll
        for (int i = 0; i < 2; i++)
            #pragma unroll
            for (int j = 0; j < 4; j++)
                wmma::fill_fragment(cf[i][j], 0.f);
    }

    const int nk = K / GBK;

    // async stage: A 128x32 (4x16B/thread), Bh+Bl 32x128 (4x16B/thread each)
    auto stage = [&](int st, int kt) {
        #pragma unroll
        for (int i = 0; i < 4; i++) {
            int idx = tid + 256 * i;
            int r = idx >> 3, c = (idx & 7) * 4;
            cp_async16(&As[st][r][c], A + (size_t)(row0 + r) * K + kt + c);
        }
        #pragma unroll
        for (int i = 0; i < 4; i++) {
            int idx = tid + 256 * i;
            int r = idx >> 5, c = (idx & 31) * 4;
            cp_async16(&Bhs[st][r][c], Bh + (size_t)(kt + r) * Nc + col0 + c);
            cp_async16(&Bls[st][r][c], Bl + (size_t)(kt + r) * Nc + col0 + c);
        }
        cp_commit();
    };

    stage(0, 0);

    for (int kt = 0; kt < nk; kt++) {
        if (kt + 1 < nk) {
            stage((kt + 1) & 1, (kt + 1) * GBK);
            cp_wait<1>();
        } else {
            cp_wait<0>();
        }
        __syncthreads();
        int st = kt & 1;

        #pragma unroll
        for (int ks = 0; ks < GBK / 8; ks++) {
            wmma::fragment<wmma::matrix_a, 16, 16, 8, wmma::precision::tf32, wmma::row_major> ah[2], al[2];
            wmma::fragment<wmma::matrix_b, 16, 16, 8, wmma::precision::tf32, wmma::row_major> bh[4], bl[4];
            #pragma unroll
            for (int i = 0; i < 2; i++) {
                wmma::load_matrix_sync(ah[i], &As[st][wm * 32 + i * 16][ks * 8], LDA);
                #pragma unroll
                for (int e = 0; e < ah[i].num_elements; e++) {
                    float v = ah[i].x[e];
                    float hi = wmma::__float_to_tf32(v);
                    ah[i].x[e] = hi;
                    al[i].x[e] = wmma::__float_to_tf32(v - hi);
                }
            }
            #pragma unroll
            for (int j = 0; j < 4; j++) {
                wmma::load_matrix_sync(bh[j], &Bhs[st][ks * 8][wn * 64 + j * 16], LDB);
                wmma::load_matrix_sync(bl[j], &Bls[st][ks * 8][wn * 64 + j * 16], LDB);
            }
            #pragma unroll
            for (int i = 0; i < 2; i++)
                #pragma unroll
                for (int j = 0; j < 4; j++) {
                    wmma::mma_sync(cf[i][j], al[i], bh[j], cf[i][j]);
                    wmma::mma_sync(cf[i][j], ah[i], bl[j], cf[i][j]);
                    wmma::mma_sync(cf[i][j], ah[i], bh[j], cf[i][j]);
                }
        }
        __syncthreads();
    }

    #pragma unroll
    for (int i = 0; i < 2; i++)
        #pragma unroll
        for (int j = 0; j < 4; j++)
            wmma::store_matrix_sync(
                C + (size_t)(row0 + wm * 32 + i * 16) * Nc + col0 + wn * 64 + j * 16,
                cf[i][j], Nc, wmma::mem_row_major);
}

// ---------------- BatchNorm ----------------
__global__ void k_bn_stats(const float* __restrict__ x, int M, int C) {
    int c = threadIdx.x;
    double s = 0.0, ss = 0.0;
    for (int r = blockIdx.x; r < M; r += gridDim.x) {
        float v = x[(size_t)r * C + c];
        s += v;
        ss += (double)v * (double)v;
    }
    atomicAdd(&g_sum[c], s);
    atomicAdd(&g_sumsq[c], ss);
}
// finalize mu/rstd and reset accumulators for the next BN (single block)
__global__ void k_bn_fin(int M, int C) {
    int c = threadIdx.x;
    if (c < C) {
        double mu = g_sum[c] / M;
        double var = g_sumsq[c] / M - mu * mu;
        g_mu[c] = (float)mu;
        g_rstd[c] = rsqrtf((float)var + BN_EPS);
    }
    g_sum[threadIdx.x] = 0.0;
    g_sumsq[threadIdx.x] = 0.0;
}
__global__ void k_bn_apply(const float4* __restrict__ x, float4* __restrict__ y,
                           const float4* __restrict__ gam, const float4* __restrict__ bet,
                           int M, int C4, int do_relu) {
    size_t idx = (size_t)blockIdx.x * blockDim.x + threadIdx.x;
    if (idx >= (size_t)M * C4) return;
    int c4 = (int)(idx % C4);
    float4 v = x[idx];
    float4 mu = ((const float4*)g_mu)[c4];
    float4 rs = ((const float4*)g_rstd)[c4];
    float4 g = __ldg(&gam[c4]);
    float4 b = __ldg(&bet[c4]);
    v.x = (v.x - mu.x) * rs.x * g.x + b.x;
    v.y = (v.y - mu.y) * rs.y * g.y + b.y;
    v.z = (v.z - mu.z) * rs.z * g.z + b.z;
    v.w = (v.w - mu.w) * rs.w * g.w + b.w;
    if (do_relu) {
        v.x = fmaxf(v.x, 0.f); v.y = fmaxf(v.y, 0.f);
        v.z = fmaxf(v.z, 0.f); v.w = fmaxf(v.w, 0.f);
    }
    y[idx] = v;
}

// ---------------- final BN + pool + linear ----------------
__global__ void k_pool(const float* __restrict__ h, const int* __restrict__ batch,
                       const float* __restrict__ predW,
                       const float* __restrict__ gam, const float* __restrict__ bet) {
    int g = blockIdx.x * blockDim.x + threadIdx.x;
    int node = g >> 5;
    int lane = g & 31;
    if (node >= NN) return;
    float acc = 0.f;
    #pragma unroll
    for (int d = lane; d < DD; d += 32) {
        float v = (h[(size_t)node * DD + d] - g_mu[d]) * g_rstd[d] * gam[d] + bet[d];
        acc += v * predW[d];
    }
    #pragma unroll
    for (int o = 16; o > 0; o >>= 1) acc += __shfl_down_sync(0xffffffffu, acc, o);
    if (lane == 0) {
        int b = batch[node];
        atomicAdd(&g_pool[b], acc);
        atomicAdd(&g_cnt[b], 1);
    }
}
__global__ void k_finish(float* __restrict__ out, const float* __restrict__ predb) {
    int g = blockIdx.x * blockDim.x + threadIdx.x;
    if (g < NG) out[g] = g_pool[g] / fmaxf((float)g_cnt[g], 1.f) + predb[0];
}

// ---------------- host driver ----------------
template <typename T>
static T* symaddr(const void* sym) {
    void* p = nullptr;
    cudaGetSymbolAddress(&p, sym);
    return (T*)p;
}

extern "C" void kernel_launch(void* const* d_in, const int* in_sizes, int n_in,
                              void* d_out, int out_size) {
    const int*   x     = (const int*)d_in[0];
    const int*   ei    = (const int*)d_in[1];
    const int*   ea    = (const int*)d_in[2];
    const int*   batch = (const int*)d_in[3];
    const float* atom  = (const float*)d_in[4];
    const float* bond  = (const float*)d_in[5];
    const float* W1    = (const float*)d_in[6];
    // b1 = d_in[7] : cancelled by BatchNorm (per-channel constant)
    const float* g1    = (const float*)d_in[8];
    const float* be1   = (const float*)d_in[9];
    const float* W2    = (const float*)d_in[10];
    // b2 = d_in[11] : cancelled by BatchNorm
    const float* g2    = (const float*)d_in[12];
    const float* be2   = (const float*)d_in[13];
    const float* W3    = (const float*)d_in[14];
    // b3 = d_in[15] : only enters the residual stream; cancelled at every BN
    const float* t     = (const float*)d_in[16];
    const float* ng    = (const float*)d_in[17];
    const float* nb    = (const float*)d_in[18];
    const float* predW = (const float*)d_in[19];
    const float* predb = (const float*)d_in[20];
    float* out = (float*)d_out;

    const int* src = ei;
    const int* dst = ei + NE;

    float* ph  = symaddr<float>(g_h);
    float* ph2 = symaddr<float>(g_h2);
    float* phh = symaddr<float>(g_hh);
    float* pa1 = symaddr<float>(g_a1);
    float* pa2 = symaddr<float>(g_a2);
    float* pWh = symaddr<float>(g_Wh);
    float* pWl = symaddr<float>(g_Wl);

    float* pW1h = pWh;                    float* pW1l = pWl;
    float* pW2h = pWh + W1_ELEMS;         float* pW2l = pWl + W1_ELEMS;
    float* pW3h = pWh + W1_ELEMS + W2_ELEMS;
    float* pW3l = pWl + W1_ELEMS + W2_ELEMS;

    cudaFuncSetAttribute(k_gemm_tf32x3,
                         cudaFuncAttributeMaxDynamicSharedMemorySize, SMEM_GEMM);

    // ---- init + weight pre-split + CSR build ----
    k_init<<<(NN + 255) / 256, 256>>>();
    k_split<<<(W1_ELEMS + 255) / 256, 256>>>(W1, pW1h, pW1l, W1_ELEMS);
    k_split<<<(W2_ELEMS + 255) / 256, 256>>>(W2, pW2h, pW2l, W2_ELEMS);
    k_split<<<(W3_ELEMS + 255) / 256, 256>>>(W3, pW3h, pW3l, W3_ELEMS);
    k_count_deg<<<(NE + 255) / 256, 256>>>(dst);
    k_scanA<<<SCAN_NB, SCAN_CHUNK>>>();
    k_scanB<<<1, 256>>>();
    k_scanC<<<SCAN_NB, SCAN_CHUNK>>>();
    k_fill<<<(NE + 255) / 256, 256>>>(dst);

    // ---- atom encoder ----
    k_atom<<<NN, DD>>>(x, atom, ph);

    const int GM = MP / 128;   // 782

    for (int l = 0; l < NL; l++) {
        const float* hin;
        if (l == 0) {
            hin = ph;
        } else {
            k_bn_stats<<<512, DD>>>(ph, NN, DD);
            k_bn_fin<<<1, HH>>>(NN, DD);
            k_bn_apply<<<(int)(((size_t)NN * (DD/4) + 255) / 256), 256>>>(
                (const float4*)ph, (float4*)ph2,
                (const float4*)(ng + (size_t)(l - 1) * DD),
                (const float4*)(nb + (size_t)(l - 1) * DD), NN, DD/4, 1);
            hin = ph2;
        }

        k_msg<<<NN, DD>>>(hin, src, ea, bond + (size_t)l * 3 * 6 * DD, t + l, phh);

        // GEMM1: [MP,128]x[128,256]
        k_gemm_tf32x3<<<dim3(GM, HH / 128), 256, SMEM_GEMM>>>(
            phh, pW1h + (size_t)l * DD * HH, pW1l + (size_t)l * DD * HH,
            nullptr, pa1, DD, HH);
        k_bn_stats<<<512, HH>>>(pa1, NN, HH);
        k_bn_fin<<<1, HH>>>(NN, HH);
        k_bn_apply<<<(int)(((size_t)NN * (HH/4) + 255) / 256), 256>>>(
            (const float4*)pa1, (float4*)pa1,
            (const float4*)(g1 + (size_t)l * HH),
            (const float4*)(be1 + (size_t)l * HH), NN, HH/4, 1);

        // GEMM2: [MP,256]x[256,256]
        k_gemm_tf32x3<<<dim3(GM, HH / 128), 256, SMEM_GEMM>>>(
            pa1, pW2h + (size_t)l * HH * HH, pW2l + (size_t)l * HH * HH,
            nullptr, pa2, HH, HH);
        k_bn_stats<<<512, HH>>>(pa2, NN, HH);
        k_bn_fin<<<1, HH>>>(NN, HH);
        k_bn_apply<<<(int)(((size_t)NN * (HH/4) + 255) / 256), 256>>>(
            (const float4*)pa2, (float4*)pa2,
            (const float4*)(g2 + (size_t)l * HH),
            (const float4*)(be2 + (size_t)l * HH), NN, HH/4, 1);

        // GEMM3: [MP,256]x[256,128] (+ residual for l>=1), writes h in place
        k_gemm_tf32x3<<<dim3(GM, DD / 128), 256, SMEM_GEMM>>>(
            pa2, pW3h + (size_t)l * HH * DD, pW3l + (size_t)l * HH * DD,
            (l > 0) ? ph : nullptr, ph, HH, DD);
    }

    // ---- final BN + pool + prediction ----
    k_bn_stats<<<512, DD>>>(ph, NN, DD);
    k_bn_fin<<<1, HH>>>(NN, DD);
    k_pool<<<(NN * 32 + 255) / 256, 256>>>(ph, batch, predW,
                                           ng + (size_t)(NL - 1) * DD,
                                           nb + (size_t)(NL - 1) * DD);
    k_finish<<<(NG + 255) / 256, 256>>>(out, predb);
}

// round 16
// speedup vs baseline: 1.2857x; 1.2857x over previous
#include <cuda_runtime.h>
#include <cuda_bf16.h>
#include <cstdint>
#include <mma.h>
#include <math.h>

using namespace nvcuda;

#define NN 100000
#define MP 100096          // padded to 782*128
#define NE 400000
#define NG 4096
#define DD 128
#define HH 256
#define NL 20
#define G_EPS 1e-7f
#define BN_EPS 1e-5f

#define W1_ELEMS (NL*DD*HH)
#define W2_ELEMS (NL*HH*HH)
#define W3_ELEMS (NL*HH*DD)
#define W_TOTAL  (W1_ELEMS + W2_ELEMS + W3_ELEMS)

// ---------------- scratch (device globals; no allocations) ----------------
__device__ float g_h [MP*DD];
__device__ float g_h2[MP*DD];
__device__ float g_a1[MP*HH];
__device__ float g_a2[MP*HH];
__device__ __nv_bfloat16 g_Ab1[(size_t)3 * MP * DD];  // GEMM1 input planes (K=128)
__device__ __nv_bfloat16 g_Ab2[(size_t)3 * MP * HH];  // GEMM2/3 input planes (K=256)
__device__ __nv_bfloat16 g_Wb[(size_t)3 * W_TOTAL];   // weight planes, [K,N] layout
__device__ double g_sum[HH];
__device__ double g_sumsq[HH];
__device__ float g_mu[HH];
__device__ float g_rstd[HH];
__device__ int   g_deg[NN];
__device__ int   g_off[NN+1];
__device__ int   g_cursor[NN];
__device__ int   g_eid[NE];
__device__ int   g_partial[256];
__device__ float g_pool[NG];
__device__ int   g_cnt[NG];

#define SCAN_CHUNK 512
#define SCAN_NB ((NN + SCAN_CHUNK - 1) / SCAN_CHUNK)   // 196

// ---------------- small utility kernels ----------------
__global__ void k_init() {
    int i = blockIdx.x * blockDim.x + threadIdx.x;
    if (i < NN) { g_deg[i] = 0; g_cursor[i] = 0; }
    if (i < NG) { g_pool[i] = 0.f; g_cnt[i] = 0; }
    if (i < HH) { g_sum[i] = 0.0; g_sumsq[i] = 0.0; }
}

// ---------------- bf16 3-way split ----------------
__device__ __forceinline__ void bf16x3(float v, __nv_bfloat16& t1,
                                       __nv_bfloat16& t2, __nv_bfloat16& t3) {
    t1 = __float2bfloat16(v);
    float r = v - __bfloat162float(t1);
    t2 = __float2bfloat16(r);
    float r2 = r - __bfloat162float(t2);
    t3 = __float2bfloat16(r2);
}

// elementwise split (used for weights; [K,N] layout preserved)
__global__ void k_split(const float* __restrict__ x,
                        __nv_bfloat16* __restrict__ o0,
                        __nv_bfloat16* __restrict__ o1,
                        __nv_bfloat16* __restrict__ o2, int n) {
    int i = blockIdx.x * blockDim.x + threadIdx.x;
    if (i >= n) return;
    __nv_bfloat16 t1, t2, t3;
    bf16x3(x[i], t1, t2, t3);
    o0[i] = t1; o1[i] = t2; o2[i] = t3;
}

// ---------------- CSR build ----------------
__global__ void k_count_deg(const int* __restrict__ dst) {
    int e = blockIdx.x * blockDim.x + threadIdx.x;
    if (e < NE) atomicAdd(&g_deg[dst[e]], 1);
}
__global__ void k_scanA() {
    __shared__ int sm[SCAN_CHUNK];
    int tid = threadIdx.x;
    int gi = blockIdx.x * SCAN_CHUNK + tid;
    sm[tid] = (gi < NN) ? g_deg[gi] : 0;
    __syncthreads();
    for (int s = SCAN_CHUNK / 2; s > 0; s >>= 1) {
        if (tid < s) sm[tid] += sm[tid + s];
        __syncthreads();
    }
    if (tid == 0) g_partial[blockIdx.x] = sm[0];
}
__global__ void k_scanB() {
    __shared__ int sp[256];
    int tid = threadIdx.x;
    if (tid < SCAN_NB) sp[tid] = g_partial[tid];
    __syncthreads();
    if (tid == 0) {
        int run = 0;
        for (int i = 0; i < SCAN_NB; i++) { int v = sp[i]; sp[i] = run; run += v; }
        g_off[NN] = run;
    }
    __syncthreads();
    if (tid < SCAN_NB) g_partial[tid] = sp[tid];
}
__global__ void k_scanC() {
    __shared__ int sm[SCAN_CHUNK];
    int tid = threadIdx.x;
    int gi = blockIdx.x * SCAN_CHUNK + tid;
    int v = (gi < NN) ? g_deg[gi] : 0;
    sm[tid] = v;
    __syncthreads();
    for (int o = 1; o < SCAN_CHUNK; o <<= 1) {
        int t = (tid >= o) ? sm[tid - o] : 0;
        __syncthreads();
        sm[tid] += t;
        __syncthreads();
    }
    if (gi < NN) g_off[gi] = sm[tid] - v + g_partial[blockIdx.x];
}
__global__ void k_fill(const int* __restrict__ dst) {
    int e = blockIdx.x * blockDim.x + threadIdx.x;
    if (e < NE) {
        int d = dst[e];
        int p = atomicAdd(&g_cursor[d], 1);
        g_eid[g_off[d] + p] = e;
    }
}

// ---------------- atom encoder ----------------
__global__ void k_atom(const int* __restrict__ x, const float* __restrict__ emb,
                       float* __restrict__ h) {
    int n = blockIdx.x;
    int d = threadIdx.x;
    float s = 0.f;
    #pragma unroll
    for (int i = 0; i < 9; i++) {
        int id = x[n * 9 + i];
        s += emb[((size_t)i * 119 + id) * DD + d];
    }
    h[(size_t)n * DD + d] = s;
}

// -------- message + scatter softmax; emits bf16x3 planes for GEMM1 --------
__global__ void k_msg(const float* __restrict__ h, const int* __restrict__ src,
                      const int* __restrict__ ea, const float* __restrict__ bond,
                      const float* __restrict__ tptr,
                      __nv_bfloat16* __restrict__ o0, __nv_bfloat16* __restrict__ o1,
                      __nv_bfloat16* __restrict__ o2) {
    __shared__ int ssrc[128];
    __shared__ int spack[128];
    int n = blockIdx.x;
    int d = threadIdx.x;
    float tv = __ldg(tptr);
    int beg = g_off[n], end = g_off[n + 1];
    float mrun = -3.4e38f;
    float dsum = 0.f, nsum = 0.f;
    for (int base = beg; base < end; base += 128) {
        int j = base + d;
        if (j < end) {
            int e = g_eid[j];
            ssrc[d]  = src[e];
            spack[d] = ea[e * 3 + 0] | (ea[e * 3 + 1] << 8) | (ea[e * 3 + 2] << 16);
        }
        __syncthreads();
        int cnt = min(end - base, 128);
        for (int jj = 0; jj < cnt; jj++) {
            int s = ssrc[jj];
            int pk = spack[jj];
            int a0 = pk & 255, a1 = (pk >> 8) & 255, a2 = pk >> 16;
            float m = __ldg(&h[(size_t)s * DD + d])
                    + __ldg(&bond[(size_t)a0 * DD + d])
                    + __ldg(&bond[(size_t)(6 + a1) * DD + d])
                    + __ldg(&bond[(size_t)(12 + a2) * DD + d]);
            m = fmaxf(m, 0.f) + G_EPS;
            float sc = m * tv;
            if (sc > mrun) {
                float corr = __expf(mrun - sc);
                dsum *= corr; nsum *= corr; mrun = sc;
            }
            float ex = __expf(sc - mrun);
            dsum += ex;
            nsum += m * ex;
        }
        __syncthreads();
    }
    float mo = (end > beg) ? (nsum / fmaxf(dsum, G_EPS)) : 0.f;
    float v = h[(size_t)n * DD + d] + mo;
    __nv_bfloat16 t1, t2, t3;
    bf16x3(v, t1, t2, t3);
    size_t o = (size_t)n * DD + d;
    o0[o] = t1; o1[o] = t2; o2[o] = t3;
}

// ---------------- cp.async helpers ----------------
__device__ __forceinline__ void cp_async16(unsigned dst, const void* gmem) {
    asm volatile("cp.async.ca.shared.global [%0], [%1], 16;\n" :: "r"(dst), "l"(gmem));
}
__device__ __forceinline__ void cp_commit() {
    asm volatile("cp.async.commit_group;\n");
}
template <int N>
__device__ __forceinline__ void cp_wait() {
    asm volatile("cp.async.wait_group %0;\n" :: "n"(N));
}

// -------- bf16x3 6-term WMMA GEMM, cp.async double-buffered ----------------
// C = A@B (+resid). A planes [M,K] bf16, B planes [K,N] bf16, fp32 accum.
// 6 kept terms: a1b1, a1b2, a2b1, a1b3, a2b2, a3b1 (residual ~2^-26).
// Block 128x128, GBK=32. A smem ld=40 elems (80B rows, 16B aligned),
// B ld=136 (272B). Stage bytes: 3*10240 + 3*8704 = 56832; 2 stages = 113664.
#define STG_BYTES 56832
#define SMEM_GEMM (2 * STG_BYTES)

__global__ __launch_bounds__(256) void k_gemm_b16(
    const __nv_bfloat16* __restrict__ A0, const __nv_bfloat16* __restrict__ A1,
    const __nv_bfloat16* __restrict__ A2,
    const __nv_bfloat16* __restrict__ B0, const __nv_bfloat16* __restrict__ B1,
    const __nv_bfloat16* __restrict__ B2,
    const float* __restrict__ resid, float* __restrict__ C,
    int K, int Nc)
{
    extern __shared__ char smem[];
    unsigned sb = (unsigned)__cvta_generic_to_shared(smem);
    int tid = threadIdx.x;
    int wid = tid >> 5;
    int wm = wid & 3;        // warp row: 32 rows each
    int wn = wid >> 2;       // warp col: 64 cols each
    int row0 = blockIdx.x * 128;
    int col0 = blockIdx.y * 128;

    const __nv_bfloat16* Ap[3] = {A0, A1, A2};
    const __nv_bfloat16* Bp[3] = {B0, B1, B2};

    wmma::fragment<wmma::accumulator, 16, 16, 16, float> cf[2][4];
    if (resid) {
        #pragma unroll
        for (int i = 0; i < 2; i++)
            #pragma unroll
            for (int j = 0; j < 4; j++)
                wmma::load_matrix_sync(cf[i][j],
                    resid + (size_t)(row0 + wm * 32 + i * 16) * Nc + col0 + wn * 64 + j * 16,
                    Nc, wmma::mem_row_major);
    } else {
        #pragma unroll
        for (int i = 0; i < 2; i++)
            #pragma unroll
            for (int j = 0; j < 4; j++)
                wmma::fill_fragment(cf[i][j], 0.f);
    }

    const int nk = K / 32;

    auto stage = [&](int st, int kt) {
        unsigned base = sb + st * STG_BYTES;
        // A: 3 planes x 128 rows x 4 chunks of 16B per 32-elem row
        #pragma unroll
        for (int i = 0; i < 6; i++) {
            int id = tid + 256 * i;          // 0..1535
            int pl = id >> 9;
            int rem = id & 511;
            int r = rem >> 2, c = rem & 3;
            cp_async16(base + pl * 10240 + r * 80 + c * 16,
                       Ap[pl] + (size_t)(row0 + r) * K + kt * 32 + c * 8);
        }
        // B: 3 planes x 32 rows x 16 chunks
        #pragma unroll
        for (int i = 0; i < 6; i++) {
            int id = tid + 256 * i;
            int pl = id >> 9;
            int rem = id & 511;
            int r = rem >> 4, c = rem & 15;
            cp_async16(base + 30720 + pl * 8704 + r * 272 + c * 16,
                       Bp[pl] + (size_t)(kt * 32 + r) * Nc + col0 + c * 8);
        }
        cp_commit();
    };

    stage(0, 0);

    for (int kt = 0; kt < nk; kt++) {
        if (kt + 1 < nk) {
            stage((kt + 1) & 1, kt + 1);
            cp_wait<1>();
        } else {
            cp_wait<0>();
        }
        __syncthreads();
        int st = kt & 1;
        const __nv_bfloat16* sA = (const __nv_bfloat16*)(smem + st * STG_BYTES);
        const __nv_bfloat16* sB = (const __nv_bfloat16*)(smem + st * STG_BYTES + 30720);

        #pragma unroll
        for (int ks = 0; ks < 2; ks++) {
            wmma::fragment<wmma::matrix_a, 16, 16, 16, __nv_bfloat16, wmma::row_major> af[3][2];
            #pragma unroll
            for (int p = 0; p < 3; p++)
                #pragma unroll
                for (int i = 0; i < 2; i++)
                    wmma::load_matrix_sync(af[p][i],
                        sA + p * 5120 + (wm * 32 + i * 16) * 40 + ks * 16, 40);
            #pragma unroll
            for (int bp = 0; bp < 3; bp++) {
                wmma::fragment<wmma::matrix_b, 16, 16, 16, __nv_bfloat16, wmma::row_major> bf[4];
                #pragma unroll
                for (int j = 0; j < 4; j++)
                    wmma::load_matrix_sync(bf[j],
                        sB + bp * 4352 + (ks * 16) * 136 + wn * 64 + j * 16, 136);
                for (int ap = 0; ap < 3 - bp; ap++)
                    #pragma unroll
                    for (int i = 0; i < 2; i++)
                        #pragma unroll
                        for (int j = 0; j < 4; j++)
                            wmma::mma_sync(cf[i][j], af[ap][i], bf[j], cf[i][j]);
            }
        }
        __syncthreads();
    }

    #pragma unroll
    for (int i = 0; i < 2; i++)
        #pragma unroll
        for (int j = 0; j < 4; j++)
            wmma::store_matrix_sync(
                C + (size_t)(row0 + wm * 32 + i * 16) * Nc + col0 + wn * 64 + j * 16,
                cf[i][j], Nc, wmma::mem_row_major);
}

// ---------------- BatchNorm ----------------
__global__ void k_bn_stats(const float* __restrict__ x, int M, int C) {
    int c = threadIdx.x;
    double s = 0.0, ss = 0.0;
    for (int r = blockIdx.x; r < M; r += gridDim.x) {
        float v = x[(size_t)r * C + c];
        s += v;
        ss += (double)v * (double)v;
    }
    atomicAdd(&g_sum[c], s);
    atomicAdd(&g_sumsq[c], ss);
}
__global__ void k_bn_fin(int M, int C) {
    int c = threadIdx.x;
    if (c < C) {
        double mu = g_sum[c] / M;
        double var = g_sumsq[c] / M - mu * mu;
        g_mu[c] = (float)mu;
        g_rstd[c] = rsqrtf((float)var + BN_EPS);
    }
    g_sum[threadIdx.x] = 0.0;
    g_sumsq[threadIdx.x] = 0.0;
}
// fp32-output variant (pre-message BN)
__global__ void k_bn_apply(const float4* __restrict__ x, float4* __restrict__ y,
                           const float4* __restrict__ gam, const float4* __restrict__ bet,
                           int M, int C4, int do_relu) {
    size_t idx = (size_t)blockIdx.x * blockDim.x + threadIdx.x;
    if (idx >= (size_t)M * C4) return;
    int c4 = (int)(idx % C4);
    float4 v = x[idx];
    float4 mu = ((const float4*)g_mu)[c4];
    float4 rs = ((const float4*)g_rstd)[c4];
    float4 g = __ldg(&gam[c4]);
    float4 b = __ldg(&bet[c4]);
    v.x = (v.x - mu.x) * rs.x * g.x + b.x;
    v.y = (v.y - mu.y) * rs.y * g.y + b.y;
    v.z = (v.z - mu.z) * rs.z * g.z + b.z;
    v.w = (v.w - mu.w) * rs.w * g.w + b.w;
    if (do_relu) {
        v.x = fmaxf(v.x, 0.f); v.y = fmaxf(v.y, 0.f);
        v.z = fmaxf(v.z, 0.f); v.w = fmaxf(v.w, 0.f);
    }
    y[idx] = v;
}
// bf16x3-plane-output variant (relu + split fused; feeds next GEMM)
__global__ void k_bn_apply_b16(const float4* __restrict__ x,
                               __nv_bfloat16* __restrict__ o0,
                               __nv_bfloat16* __restrict__ o1,
                               __nv_bfloat16* __restrict__ o2,
                               const float4* __restrict__ gam, const float4* __restrict__ bet,
                               int M, int C4) {
    size_t idx = (size_t)blockIdx.x * blockDim.x + threadIdx.x;
    if (idx >= (size_t)M * C4) return;
    int c4 = (int)(idx % C4);
    float4 v = x[idx];
    float4 mu = ((const float4*)g_mu)[c4];
    float4 rs = ((const float4*)g_rstd)[c4];
    float4 g = __ldg(&gam[c4]);
    float4 b = __ldg(&bet[c4]);
    float f[4];
    f[0] = fmaxf((v.x - mu.x) * rs.x * g.x + b.x, 0.f);
    f[1] = fmaxf((v.y - mu.y) * rs.y * g.y + b.y, 0.f);
    f[2] = fmaxf((v.z - mu.z) * rs.z * g.z + b.z, 0.f);
    f[3] = fmaxf((v.w - mu.w) * rs.w * g.w + b.w, 0.f);
    union { __nv_bfloat16 h[4]; uint2 u; } p0, p1, p2;
    #pragma unroll
    for (int k = 0; k < 4; k++) bf16x3(f[k], p0.h[k], p1.h[k], p2.h[k]);
    ((uint2*)o0)[idx] = p0.u;
    ((uint2*)o1)[idx] = p1.u;
    ((uint2*)o2)[idx] = p2.u;
}

// ---------------- final BN + pool + linear ----------------
__global__ void k_pool(const float* __restrict__ h, const int* __restrict__ batch,
                       const float* __restrict__ predW,
                       const float* __restrict__ gam, const float* __restrict__ bet) {
    int g = blockIdx.x * blockDim.x + threadIdx.x;
    int node = g >> 5;
    int lane = g & 31;
    if (node >= NN) return;
    float acc = 0.f;
    #pragma unroll
    for (int d = lane; d < DD; d += 32) {
        float v = (h[(size_t)node * DD + d] - g_mu[d]) * g_rstd[d] * gam[d] + bet[d];
        acc += v * predW[d];
    }
    #pragma unroll
    for (int o = 16; o > 0; o >>= 1) acc += __shfl_down_sync(0xffffffffu, acc, o);
    if (lane == 0) {
        int b = batch[node];
        atomicAdd(&g_pool[b], acc);
        atomicAdd(&g_cnt[b], 1);
    }
}
__global__ void k_finish(float* __restrict__ out, const float* __restrict__ predb) {
    int g = blockIdx.x * blockDim.x + threadIdx.x;
    if (g < NG) out[g] = g_pool[g] / fmaxf((float)g_cnt[g], 1.f) + predb[0];
}

// ---------------- host driver ----------------
template <typename T>
static T* symaddr(const void* sym) {
    void* p = nullptr;
    cudaGetSymbolAddress(&p, sym);
    return (T*)p;
}

extern "C" void kernel_launch(void* const* d_in, const int* in_sizes, int n_in,
                              void* d_out, int out_size) {
    const int*   x     = (const int*)d_in[0];
    const int*   ei    = (const int*)d_in[1];
    const int*   ea    = (const int*)d_in[2];
    const int*   batch = (const int*)d_in[3];
    const float* atom  = (const float*)d_in[4];
    const float* bond  = (const float*)d_in[5];
    const float* W1    = (const float*)d_in[6];
    // b1/b2/b3 cancelled by BatchNorm (see R2 analysis)
    const float* g1    = (const float*)d_in[8];
    const float* be1   = (const float*)d_in[9];
    const float* W2    = (const float*)d_in[10];
    const float* g2    = (const float*)d_in[12];
    const float* be2   = (const float*)d_in[13];
    const float* W3    = (const float*)d_in[14];
    const float* t     = (const float*)d_in[16];
    const float* ng    = (const float*)d_in[17];
    const float* nb    = (const float*)d_in[18];
    const float* predW = (const float*)d_in[19];
    const float* predb = (const float*)d_in[20];
    float* out = (float*)d_out;

    const int* src = ei;
    const int* dst = ei + NE;

    float* ph  = symaddr<float>(g_h);
    float* ph2 = symaddr<float>(g_h2);
    float* pa1 = symaddr<float>(g_a1);
    float* pa2 = symaddr<float>(g_a2);
    __nv_bfloat16* pA1 = symaddr<__nv_bfloat16>(g_Ab1);
    __nv_bfloat16* pA2 = symaddr<__nv_bfloat16>(g_Ab2);
    __nv_bfloat16* pWb = symaddr<__nv_bfloat16>(g_Wb);

    __nv_bfloat16* Wp0 = pWb;
    __nv_bfloat16* Wp1 = pWb + (size_t)W_TOTAL;
    __nv_bfloat16* Wp2 = pWb + (size_t)2 * W_TOTAL;

    const size_t a1s = (size_t)MP * DD;   // GEMM1 plane stride
    const size_t a2s = (size_t)MP * HH;   // GEMM2/3 plane stride

    cudaFuncSetAttribute(k_gemm_b16, cudaFuncAttributeMaxDynamicSharedMemorySize, SMEM_GEMM);

    // ---- init + weight splits + CSR build ----
    k_init<<<(NN + 255) / 256, 256>>>();
    k_split<<<(W1_ELEMS + 255) / 256, 256>>>(W1, Wp0, Wp1, Wp2, W1_ELEMS);
    k_split<<<(W2_ELEMS + 255) / 256, 256>>>(W2, Wp0 + W1_ELEMS, Wp1 + W1_ELEMS,
                                             Wp2 + W1_ELEMS, W2_ELEMS);
    k_split<<<(W3_ELEMS + 255) / 256, 256>>>(W3, Wp0 + W1_ELEMS + W2_ELEMS,
                                             Wp1 + W1_ELEMS + W2_ELEMS,
                                             Wp2 + W1_ELEMS + W2_ELEMS, W3_ELEMS);
    k_count_deg<<<(NE + 255) / 256, 256>>>(dst);
    k_scanA<<<SCAN_NB, SCAN_CHUNK>>>();
    k_scanB<<<1, 256>>>();
    k_scanC<<<SCAN_NB, SCAN_CHUNK>>>();
    k_fill<<<(NE + 255) / 256, 256>>>(dst);

    k_atom<<<NN, DD>>>(x, atom, ph);

    const int GM = MP / 128;   // 782

    for (int l = 0; l < NL; l++) {
        const float* hin;
        if (l == 0) {
            hin = ph;
        } else {
            k_bn_stats<<<512, DD>>>(ph, NN, DD);
            k_bn_fin<<<1, HH>>>(NN, DD);
            k_bn_apply<<<(int)(((size_t)NN * (DD/4) + 255) / 256), 256>>>(
                (const float4*)ph, (float4*)ph2,
                (const float4*)(ng + (size_t)(l - 1) * DD),
                (const float4*)(nb + (size_t)(l - 1) * DD), NN, DD/4, 1);
            hin = ph2;
        }

        // message pass writes GEMM1 input planes directly
        k_msg<<<NN, DD>>>(hin, src, ea, bond + (size_t)l * 3 * 6 * DD, t + l,
                          pA1, pA1 + a1s, pA1 + 2 * a1s);

        // GEMM1: [MP,128] @ W1[128,256]
        {
            size_t wo = (size_t)l * DD * HH;
            k_gemm_b16<<<dim3(GM, HH / 128), 256, SMEM_GEMM>>>(
                pA1, pA1 + a1s, pA1 + 2 * a1s,
                Wp0 + wo, Wp1 + wo, Wp2 + wo, nullptr, pa1, DD, HH);
        }
        k_bn_stats<<<512, HH>>>(pa1, NN, HH);
        k_bn_fin<<<1, HH>>>(NN, HH);
        k_bn_apply_b16<<<(int)(((size_t)NN * (HH/4) + 255) / 256), 256>>>(
            (const float4*)pa1, pA2, pA2 + a2s, pA2 + 2 * a2s,
            (const float4*)(g1 + (size_t)l * HH),
            (const float4*)(be1 + (size_t)l * HH), NN, HH/4);

        // GEMM2: [MP,256] @ W2[256,256]
        {
            size_t wo = (size_t)W1_ELEMS + (size_t)l * HH * HH;
            k_gemm_b16<<<dim3(GM, HH / 128), 256, SMEM_GEMM>>>(
                pA2, pA2 + a2s, pA2 + 2 * a2s,
                Wp0 + wo, Wp1 + wo, Wp2 + wo, nullptr, pa2, HH, HH);
        }
        k_bn_stats<<<512, HH>>>(pa2, NN, HH);
        k_bn_fin<<<1, HH>>>(NN, HH);
        k_bn_apply_b16<<<(int)(((size_t)NN * (HH/4) + 255) / 256), 256>>>(
            (const float4*)pa2, pA2, pA2 + a2s, pA2 + 2 * a2s,
            (const float4*)(g2 + (size_t)l * HH),
            (const float4*)(be2 + (size_t)l * HH), NN, HH/4);

        // GEMM3: [MP,256] @ W3[256,128] (+resid for l>=1), writes h in place
        {
            size_t wo = (size_t)W1_ELEMS + W2_ELEMS + (size_t)l * HH * DD;
            k_gemm_b16<<<dim3(GM, DD / 128), 256, SMEM_GEMM>>>(
                pA2, pA2 + a2s, pA2 + 2 * a2s,
                Wp0 + wo, Wp1 + wo, Wp2 + wo, (l > 0) ? ph : nullptr, ph, HH, DD);
        }
    }

    // ---- final BN + pool + prediction ----
    k_bn_stats<<<512, DD>>>(ph, NN, DD);
    k_bn_fin<<<1, HH>>>(NN, DD);
    k_pool<<<(NN * 32 + 255) / 256, 256>>>(ph, batch, predW,
                                           ng + (size_t)(NL - 1) * DD,
                                           nb + (size_t)(NL - 1) * DD);
    k_finish<<<(NG + 255) / 256, 256>>>(out, predb);
}